// round 8
// baseline (speedup 1.0000x reference)
#include <cuda_runtime.h>

#define NPL   50000
#define L_TOT 6
#define KN    8
#define FEAT  32
#define H     128
#define MT    32      // nodes per block = 4 warps x 8
#define NT    128
#define TMW   8       // nodes per warp
#define SROW  36      // transposed smem row stride in floats (144B, 16B-aligned)
#define FROW  36

// duplicated-weight row offsets (each row = H ull entries, entry = (w,w))
#define RD_MP0   0
#define RD_MP1   128
#define RD_MPC   256     // + i*256
#define RD_NE0   1280
#define RD_NE1   1536
#define RD_NEC   1664    // + i*256
#define RD_TOTAL 2688

typedef unsigned long long ull;

__device__ ull g_Wd[RD_TOTAL * H];   // [row][f] = (W[row][f], W[row][f])

__device__ __forceinline__ ull pack2(float x, float y) {
    ull r; asm("mov.b64 %0, {%1, %2};" : "=l"(r) : "f"(x), "f"(y)); return r;
}
__device__ __forceinline__ void fma2(ull& acc, ull a, ull b) {
    asm("fma.rn.f32x2 %0, %1, %2, %0;" : "+l"(acc) : "l"(a), "l"(b));
}
__device__ __forceinline__ float2 unpack2(ull v) {
    float2 f; asm("mov.b64 {%0, %1}, %2;" : "=f"(f.x), "=f"(f.y) : "l"(v)); return f;
}
__device__ __forceinline__ float htanh(float x) {
    float y; asm("tanh.approx.f32 %0, %1;" : "=f"(y) : "f"(x)); return y;
}

// duplicate weights: g_Wd[row][f] = (w, w)
__global__ void dup_weights(const float* __restrict__ Wmp0, const float* __restrict__ Wmp1,
                            const float* __restrict__ Wmpc, const float* __restrict__ Wne0,
                            const float* __restrict__ Wne1, const float* __restrict__ Wnec)
{
    int idx = blockIdx.x * blockDim.x + threadIdx.x;
    if (idx >= RD_TOTAL * H) return;
    int row = idx / H, f = idx % H;
    const float* src; int local;
    if      (row < RD_MP1) { src = Wmp0;                                  local = row; }
    else if (row < RD_MPC) { src = Wmp1;                                  local = row - RD_MP1; }
    else if (row < RD_NE0) { src = Wmpc + ((row - RD_MPC) / 256) * 2*H*H; local = (row - RD_MPC) % 256; }
    else if (row < RD_NE1) { src = Wne0;                                  local = row - RD_NE0; }
    else if (row < RD_NEC) { src = Wne1;                                  local = row - RD_NE1; }
    else                   { src = Wnec + ((row - RD_NEC) / 256) * 2*H*H; local = (row - RD_NEC) % 256; }
    float w = src[local * H + f];
    g_Wd[idx] = pack2(w, w);
}

// acc[p][j] += S[k][m0+2p..] * W[k][f4+j], S transposed [k][m].
// One LDS.128 = 2 node-pairs -> feeds 8 fma2; weights pre-dup'd (zero MOVs).
__device__ __forceinline__ void accum(const float* __restrict__ S,
                                      const ull* __restrict__ Wd,
                                      int f4, int m0, ull acc[4][4])
{
#pragma unroll 2
    for (int k = 0; k < H; k++) {
        ulonglong2 w01 = __ldg(reinterpret_cast<const ulonglong2*>(Wd + (size_t)k*H + f4));
        ulonglong2 w23 = __ldg(reinterpret_cast<const ulonglong2*>(Wd + (size_t)k*H + f4 + 2));
        ulonglong2 aA = *reinterpret_cast<const ulonglong2*>(S + k*SROW + m0);      // pairs (m0,m0+1),(m0+2,m0+3)
        ulonglong2 aB = *reinterpret_cast<const ulonglong2*>(S + k*SROW + m0 + 4);  // pairs (m0+4,..),(m0+6,..)
        fma2(acc[0][0], aA.x, w01.x); fma2(acc[0][1], aA.x, w01.y);
        fma2(acc[0][2], aA.x, w23.x); fma2(acc[0][3], aA.x, w23.y);
        fma2(acc[1][0], aA.y, w01.x); fma2(acc[1][1], aA.y, w01.y);
        fma2(acc[1][2], aA.y, w23.x); fma2(acc[1][3], aA.y, w23.y);
        fma2(acc[2][0], aB.x, w01.x); fma2(acc[2][1], aB.x, w01.y);
        fma2(acc[2][2], aB.x, w23.x); fma2(acc[2][3], aB.x, w23.y);
        fma2(acc[3][0], aB.y, w01.x); fma2(acc[3][1], aB.y, w01.y);
        fma2(acc[3][2], aB.y, w23.x); fma2(acc[3][3], aB.y, w23.y);
    }
}

// warp-local dense stage, transposed in/out: sO[f][m] = tanh(b[f] + sX^T.W (+ sY^T.W2))
template<bool CAT>
__device__ __forceinline__ void stage(const float* __restrict__ sX,
                                      const float* __restrict__ sY,
                                      int rowOff, const float* __restrict__ b,
                                      float* __restrict__ sO, int f4, int m0)
{
    ull acc[4][4];
    float4 bb = __ldg(reinterpret_cast<const float4*>(b + f4));
#pragma unroll
    for (int p = 0; p < 4; p++) {
        acc[p][0] = pack2(bb.x, bb.x);
        acc[p][1] = pack2(bb.y, bb.y);
        acc[p][2] = pack2(bb.z, bb.z);
        acc[p][3] = pack2(bb.w, bb.w);
    }
    accum(sX, g_Wd + (size_t)rowOff * H, f4, m0, acc);
    if (CAT) accum(sY, g_Wd + (size_t)(rowOff + H) * H, f4, m0, acc);

#pragma unroll
    for (int p = 0; p < 4; p++) {
#pragma unroll
        for (int j = 0; j < 4; j++) {
            float2 v = unpack2(acc[p][j]);
            float2 o = make_float2(htanh(v.x), htanh(v.y));
            *reinterpret_cast<float2*>(sO + (f4 + j)*SROW + m0 + 2*p) = o;
        }
    }
    __syncwarp();
}

// base = tanh(nf @ W_embed + b_embed) -> emb (= d_out), node-major (proven R2 kernel)
__global__ void __launch_bounds__(NT)
embed_kernel(const float* __restrict__ nf, const float* __restrict__ W,
             const float* __restrict__ b, float* __restrict__ out, int n_nodes)
{
    __shared__ float S[MT * FROW];
    int t    = threadIdx.x;
    int f    = t;
    int base = blockIdx.x * MT;

    for (int i = t; i < MT * FEAT; i += NT) {
        int m = i / FEAT, k = i % FEAT;
        int row = base + m;
        if (row >= n_nodes) row = n_nodes - 1;
        S[m * FROW + k] = nf[(long)row * FEAT + k];
    }
    __syncthreads();

    float acc[MT];
    float bias = __ldg(b + f);
#pragma unroll
    for (int m = 0; m < MT; m++) acc[m] = bias;

#pragma unroll 2
    for (int k = 0; k < FEAT; k += 4) {
        float w0 = __ldg(W + (k+0)*H + f);
        float w1 = __ldg(W + (k+1)*H + f);
        float w2 = __ldg(W + (k+2)*H + f);
        float w3 = __ldg(W + (k+3)*H + f);
#pragma unroll
        for (int m = 0; m < MT; m++) {
            float4 a = *reinterpret_cast<const float4*>(S + m*FROW + k);
            acc[m] = fmaf(a.x, w0, acc[m]);
            acc[m] = fmaf(a.y, w1, acc[m]);
            acc[m] = fmaf(a.z, w2, acc[m]);
            acc[m] = fmaf(a.w, w3, acc[m]);
        }
    }
#pragma unroll
    for (int m = 0; m < MT; m++) {
        int row = base + m;
        if (row < n_nodes) out[(long)row * H + f] = htanh(acc[m]);
    }
}

// Full GNN layer: warp-local throughout (warp owns 8 nodes, all features), zero __syncthreads.
__global__ void __launch_bounds__(NT, 4)
layer_kernel(float* emb, const int* __restrict__ src, int lyr,
             const float* __restrict__ bmp0, const float* __restrict__ bmp1,
             const float* __restrict__ bmpc,
             const float* __restrict__ bne0, const float* __restrict__ bne1,
             const float* __restrict__ bnec)
{
    extern __shared__ float smem[];
    float* A = smem;                  // transposed [H][SROW]
    float* B = A + H * SROW;
    float* C = B + H * SROW;
    int*   sidx = (int*)(C + H * SROW);   // [MT*KN]

    int t    = threadIdx.x;
    int lane = t & 31;
    int wrp  = t >> 5;
    int f4   = lane * 4;
    int m0   = wrp * TMW;
    int d0   = blockIdx.x * MT;

    // warp-local edge indices (64 per warp)
    const int* __restrict__ srcL = src + (long)(lyr - 1) * NPL * KN;
    {
        int* sw = sidx + wrp * (TMW * KN);
#pragma unroll
        for (int j = 0; j < 2; j++) {
            int i = lane + j * 32;
            int node = d0 + m0 + i / KN;
            if (node >= NPL) node = NPL - 1;
            sw[i] = srcL[(long)node * KN + (i % KN)];
        }
    }
    __syncwarp();

    // gather, transposed: lane l owns features 4l..4l+3; A[k][m] = sum of 8 neighbor rows
    {
        const int* sw = sidx + wrp * (TMW * KN);
#pragma unroll 2
        for (int m = 0; m < TMW; m++) {
            float4 s = make_float4(0.f, 0.f, 0.f, 0.f);
#pragma unroll
            for (int k = 0; k < KN; k++) {
                int row = sw[m * KN + k];
                float4 v = __ldg(reinterpret_cast<const float4*>(emb + (long)row * H + f4));
                s.x += v.x; s.y += v.y; s.z += v.z; s.w += v.w;
            }
            A[(f4+0)*SROW + m0 + m] = s.x;
            A[(f4+1)*SROW + m0 + m] = s.y;
            A[(f4+2)*SROW + m0 + m] = s.z;
            A[(f4+3)*SROW + m0 + m] = s.w;
        }
    }
    __syncwarp();

    // message-passing MLP
    stage<false>(A, nullptr, RD_MP0, bmp0, B, f4, m0);
    stage<false>(B, nullptr, RD_MP1, bmp1, C, f4, m0);
    stage<true >(C, B, RD_MPC + 0*256, bmpc + 0*H, A, f4, m0);
    stage<true >(A, B, RD_MPC + 1*256, bmpc + 1*H, C, f4, m0);
    stage<true >(C, B, RD_MPC + 2*256, bmpc + 2*H, A, f4, m0);
    stage<true >(A, B, RD_MPC + 3*256, bmpc + 3*H, C, f4, m0);   // r -> C

    // this layer's base embedding -> A (transposed)
#pragma unroll 2
    for (int m = 0; m < TMW; m++) {
        int node = d0 + m0 + m;
        if (node >= NPL) node = NPL - 1;
        float4 v = __ldg(reinterpret_cast<const float4*>(emb + (long)(lyr * NPL + node) * H + f4));
        A[(f4+0)*SROW + m0 + m] = v.x;
        A[(f4+1)*SROW + m0 + m] = v.y;
        A[(f4+2)*SROW + m0 + m] = v.z;
        A[(f4+3)*SROW + m0 + m] = v.w;
    }
    __syncwarp();

    // node-embedding MLP
    stage<true >(A, C, RD_NE0, bne0, B, f4, m0);                 // c0 -> B
    stage<false>(B, nullptr, RD_NE1, bne1, A, f4, m0);           // e  -> A
    stage<true >(A, B, RD_NEC + 0*256, bnec + 0*H, C, f4, m0);
    stage<true >(C, B, RD_NEC + 1*256, bnec + 1*H, A, f4, m0);
    stage<true >(A, B, RD_NEC + 2*256, bnec + 2*H, C, f4, m0);
    stage<true >(C, B, RD_NEC + 3*256, bnec + 3*H, A, f4, m0);   // e -> A

    // write out: emb[lyr*NPL+node][f4..] = A^T (coalesced STG.128 across lanes)
#pragma unroll 2
    for (int m = 0; m < TMW; m++) {
        int node = d0 + m0 + m;
        if (node < NPL) {
            float4 o;
            o.x = A[(f4+0)*SROW + m0 + m];
            o.y = A[(f4+1)*SROW + m0 + m];
            o.z = A[(f4+2)*SROW + m0 + m];
            o.w = A[(f4+3)*SROW + m0 + m];
            *reinterpret_cast<float4*>(emb + (long)(lyr * NPL + node) * H + f4) = o;
        }
    }
}

extern "C" void kernel_launch(void* const* d_in, const int* in_sizes, int n_in,
                              void* d_out, int out_size)
{
    const float* nf      = (const float*)d_in[0];
    const int*   src     = (const int*)  d_in[1];
    const float* W_embed = (const float*)d_in[3];
    const float* b_embed = (const float*)d_in[4];
    const float* W_mp0   = (const float*)d_in[5];
    const float* b_mp0   = (const float*)d_in[6];
    const float* W_mp1   = (const float*)d_in[7];
    const float* b_mp1   = (const float*)d_in[8];
    const float* W_mpc   = (const float*)d_in[9];
    const float* b_mpc   = (const float*)d_in[10];
    const float* W_ne0   = (const float*)d_in[11];
    const float* b_ne0   = (const float*)d_in[12];
    const float* W_ne1   = (const float*)d_in[13];
    const float* b_ne1   = (const float*)d_in[14];
    const float* W_nec   = (const float*)d_in[15];
    const float* b_nec   = (const float*)d_in[16];

    float* out = (float*)d_out;

    const int smem_bytes = 3 * H * SROW * (int)sizeof(float) + MT * KN * (int)sizeof(int);
    cudaFuncSetAttribute(layer_kernel, cudaFuncAttributeMaxDynamicSharedMemorySize, smem_bytes);

    dup_weights<<<(RD_TOTAL * H + 255) / 256, 256>>>(W_mp0, W_mp1, W_mpc, W_ne0, W_ne1, W_nec);

    const int n_nodes = L_TOT * NPL;
    embed_kernel<<<(n_nodes + MT - 1) / MT, NT>>>(nf, W_embed, b_embed, out, n_nodes);

    const int layer_blocks = (NPL + MT - 1) / MT;
    for (int l = 1; l < L_TOT; l++) {
        layer_kernel<<<layer_blocks, NT, smem_bytes>>>(out, src, l,
                                           b_mp0, b_mp1, b_mpc, b_ne0, b_ne1, b_nec);
    }
}

// round 9
// speedup vs baseline: 3.1751x; 3.1751x over previous
#include <cuda_runtime.h>
#include <cstdint>

#define NPL   50000
#define L_TOT 6
#define KN    8
#define FEAT  32
#define H     128
#define MT    32      // nodes per block
#define NT    128     // 4 warps: warp = (16 nodes) x (64 features)
#define SROW  132     // smem row stride (floats); banks conflict-free for frag loads
#define FROW  36
#define EMT   32

#define CH_U2   8192  // uint2 per chunk = 16ks * 16nt * 32 lanes
#define N_CHUNK 21
// chunk ids
#define CK_MP0  0
#define CK_MP1  1
#define CK_MPC(i) (2 + 2*(i))    // +1 = second half (rows 128..255)
#define CK_NE0  10               // 10: blk rows, 11: r rows
#define CK_NE1  12
#define CK_NEC(i) (13 + 2*(i))

__device__ uint2 g_Wf[N_CHUNK * CH_U2];   // tf32 B-fragments: [chunk][(ks*16+nt)*32+lane] = {b0,b1}

__device__ __forceinline__ float htanh(float x) {
    float y; asm("tanh.approx.f32 %0, %1;" : "=f"(y) : "f"(x)); return y;
}
__device__ __forceinline__ uint32_t f2tf(float x) {
    uint32_t u; asm("cvt.rna.tf32.f32 %0, %1;" : "=r"(u) : "f"(x)); return u;
}
__device__ __forceinline__ void mma_tf32(float c[4], uint32_t a0, uint32_t a1,
                                         uint32_t a2, uint32_t a3,
                                         uint32_t b0, uint32_t b1) {
    asm volatile("mma.sync.aligned.m16n8k8.row.col.f32.tf32.tf32.f32 "
                 "{%0,%1,%2,%3}, {%4,%5,%6,%7}, {%8,%9}, {%0,%1,%2,%3};"
                 : "+f"(c[0]), "+f"(c[1]), "+f"(c[2]), "+f"(c[3])
                 : "r"(a0), "r"(a1), "r"(a2), "r"(a3), "r"(b0), "r"(b1));
}

// Pre-convert all MLP weights into tf32 fragment-native layout.
// B frag (k x n, col): b0 = W[8ks+tig][8nt+gid], b1 = W[8ks+tig+4][8nt+gid]
__global__ void pack_wf(const float* __restrict__ Wmp0, const float* __restrict__ Wmp1,
                        const float* __restrict__ Wmpc, const float* __restrict__ Wne0,
                        const float* __restrict__ Wne1, const float* __restrict__ Wnec)
{
    int idx = blockIdx.x * blockDim.x + threadIdx.x;
    if (idx >= N_CHUNK * CH_U2) return;
    int lane = idx & 31;
    int nt   = (idx >> 5) & 15;
    int ks   = (idx >> 9) & 15;
    int c    = idx >> 13;
    int tig = lane & 3, gid = lane >> 2;
    const float* src; int ro;
    if      (c == 0)  { src = Wmp0; ro = 0; }
    else if (c == 1)  { src = Wmp1; ro = 0; }
    else if (c < 10)  { src = Wmpc + ((c - 2) >> 1) * 2*H*H; ro = ((c - 2) & 1) * H; }
    else if (c < 12)  { src = Wne0; ro = (c - 10) * H; }
    else if (c == 12) { src = Wne1; ro = 0; }
    else              { src = Wnec + ((c - 13) >> 1) * 2*H*H; ro = ((c - 13) & 1) * H; }
    int k = 8*ks + tig, n = 8*nt + gid;
    uint2 v;
    v.x = f2tf(src[(ro + k) * H + n]);
    v.y = f2tf(src[(ro + k + 4) * H + n]);
    g_Wf[idx] = v;
}

// One dense-tanh stage on the tensor pipe.
// Warp computes D[16m x 64n] = tanh(bias + SX.W (+ SY.W2)); smem layout [m][k], stride SROW.
__device__ __noinline__ void mstage(const float* __restrict__ SX,
                                    const float* __restrict__ SY,
                                    int chunk, const float* __restrict__ bias,
                                    float* __restrict__ SO,
                                    int m0, int ncol0, int gid, int tig, int lane,
                                    bool cat)
{
    float c[8][4];
#pragma unroll
    for (int nt = 0; nt < 8; nt++) {
        float b0 = __ldg(bias + ncol0 + 8*nt + 2*tig);
        float b1 = __ldg(bias + ncol0 + 8*nt + 2*tig + 1);
        c[nt][0] = b0; c[nt][1] = b1; c[nt][2] = b0; c[nt][3] = b1;
    }
    int nbase = ncol0 >> 3;   // first ntile index within chunk
    {
        const uint2* Wc = g_Wf + chunk * CH_U2;
        const float* S0 = SX + (m0 + gid) * SROW + tig;
        const float* S1 = SX + (m0 + gid + 8) * SROW + tig;
#pragma unroll 2
        for (int ks = 0; ks < 16; ks++) {
            uint32_t a0 = f2tf(S0[8*ks]);
            uint32_t a1 = f2tf(S1[8*ks]);
            uint32_t a2 = f2tf(S0[8*ks + 4]);
            uint32_t a3 = f2tf(S1[8*ks + 4]);
            const uint2* wrow = Wc + (ks*16 + nbase) * 32 + lane;
#pragma unroll
            for (int nt = 0; nt < 8; nt++) {
                uint2 bb = __ldg(wrow + nt * 32);
                mma_tf32(c[nt], a0, a1, a2, a3, bb.x, bb.y);
            }
        }
    }
    if (cat) {
        const uint2* Wc = g_Wf + (chunk + 1) * CH_U2;
        const float* S0 = SY + (m0 + gid) * SROW + tig;
        const float* S1 = SY + (m0 + gid + 8) * SROW + tig;
#pragma unroll 2
        for (int ks = 0; ks < 16; ks++) {
            uint32_t a0 = f2tf(S0[8*ks]);
            uint32_t a1 = f2tf(S1[8*ks]);
            uint32_t a2 = f2tf(S0[8*ks + 4]);
            uint32_t a3 = f2tf(S1[8*ks + 4]);
            const uint2* wrow = Wc + (ks*16 + nbase) * 32 + lane;
#pragma unroll
            for (int nt = 0; nt < 8; nt++) {
                uint2 bb = __ldg(wrow + nt * 32);
                mma_tf32(c[nt], a0, a1, a2, a3, bb.x, bb.y);
            }
        }
    }
#pragma unroll
    for (int nt = 0; nt < 8; nt++) {
        int col = ncol0 + 8*nt + 2*tig;
        float2 lo = make_float2(htanh(c[nt][0]), htanh(c[nt][1]));
        float2 hi = make_float2(htanh(c[nt][2]), htanh(c[nt][3]));
        *reinterpret_cast<float2*>(SO + (m0 + gid) * SROW + col) = lo;
        *reinterpret_cast<float2*>(SO + (m0 + gid + 8) * SROW + col) = hi;
    }
}

// base = tanh(nf @ W_embed + b_embed) -> emb (= d_out)   [proven scalar kernel]
__global__ void __launch_bounds__(NT)
embed_kernel(const float* __restrict__ nf, const float* __restrict__ W,
             const float* __restrict__ b, float* __restrict__ out, int n_nodes)
{
    __shared__ float S[EMT * FROW];
    int t    = threadIdx.x;
    int f    = t;
    int base = blockIdx.x * EMT;

    for (int i = t; i < EMT * FEAT; i += NT) {
        int m = i / FEAT, k = i % FEAT;
        int row = base + m;
        if (row >= n_nodes) row = n_nodes - 1;
        S[m * FROW + k] = nf[(long)row * FEAT + k];
    }
    __syncthreads();

    float acc[EMT];
    float bias = __ldg(b + f);
#pragma unroll
    for (int m = 0; m < EMT; m++) acc[m] = bias;

#pragma unroll 2
    for (int k = 0; k < FEAT; k += 4) {
        float w0 = __ldg(W + (k+0)*H + f);
        float w1 = __ldg(W + (k+1)*H + f);
        float w2 = __ldg(W + (k+2)*H + f);
        float w3 = __ldg(W + (k+3)*H + f);
#pragma unroll
        for (int m = 0; m < EMT; m++) {
            float4 a = *reinterpret_cast<const float4*>(S + m*FROW + k);
            acc[m] = fmaf(a.x, w0, acc[m]);
            acc[m] = fmaf(a.y, w1, acc[m]);
            acc[m] = fmaf(a.z, w2, acc[m]);
            acc[m] = fmaf(a.w, w3, acc[m]);
        }
    }
#pragma unroll
    for (int m = 0; m < EMT; m++) {
        int row = base + m;
        if (row < n_nodes) out[(long)row * H + f] = htanh(acc[m]);
    }
}

// Full GNN layer on tensor pipe: gather -> 11 mma stages -> write block l.
__global__ void __launch_bounds__(NT)
layer_kernel(float* emb, const int* __restrict__ src, int lyr,
             const float* __restrict__ bmp0, const float* __restrict__ bmp1,
             const float* __restrict__ bmpc,
             const float* __restrict__ bne0, const float* __restrict__ bne1,
             const float* __restrict__ bnec)
{
    extern __shared__ float smem[];
    float* A = smem;                   // [MT][SROW]
    float* B = A + MT * SROW;
    float* C = B + MT * SROW;
    int*   sidx = (int*)(C + MT * SROW);

    int t    = threadIdx.x;
    int lane = t & 31;
    int w    = t >> 5;
    int gid  = lane >> 2;
    int tig  = lane & 3;
    int m0    = (w & 1) * 16;    // warp's node-tile
    int ncol0 = (w >> 1) * 64;   // warp's feature-tile
    int d0   = blockIdx.x * MT;

    const int* __restrict__ srcL = src + (long)(lyr - 1) * NPL * KN;
    for (int i = t; i < MT * KN; i += NT) {
        int node = d0 + i / KN;
        if (node >= NPL) node = NPL - 1;
        sidx[i] = srcL[(long)node * KN + (i % KN)];
    }
    __syncthreads();

    // gather: A[m][t] = sum of 8 neighbor rows (coalesced across t, L2-hot)
#pragma unroll 2
    for (int m = 0; m < MT; m++) {
        float s = 0.f;
#pragma unroll
        for (int k = 0; k < KN; k++) {
            int row = sidx[m * KN + k];
            s += __ldg(emb + (long)row * H + t);
        }
        A[m * SROW + t] = s;
    }
    __syncthreads();

    // message-passing MLP
    mstage(A, nullptr, CK_MP0, bmp0, B, m0, ncol0, gid, tig, lane, false); __syncthreads(); // r0->B
    mstage(B, nullptr, CK_MP1, bmp1, C, m0, ncol0, gid, tig, lane, false); __syncthreads(); // r ->C
    mstage(C, B, CK_MPC(0), bmpc + 0*H, A, m0, ncol0, gid, tig, lane, true); __syncthreads();
    mstage(A, B, CK_MPC(1), bmpc + 1*H, C, m0, ncol0, gid, tig, lane, true); __syncthreads();
    mstage(C, B, CK_MPC(2), bmpc + 2*H, A, m0, ncol0, gid, tig, lane, true); __syncthreads();
    mstage(A, B, CK_MPC(3), bmpc + 3*H, C, m0, ncol0, gid, tig, lane, true); __syncthreads(); // r->C

    // this layer's base embedding -> A
#pragma unroll 2
    for (int m = 0; m < MT; m++) {
        int node = d0 + m;
        if (node >= NPL) node = NPL - 1;
        A[m * SROW + t] = __ldg(emb + (long)(lyr * NPL + node) * H + t);
    }
    __syncthreads();

    // node-embedding MLP
    mstage(A, C, CK_NE0, bne0, B, m0, ncol0, gid, tig, lane, true); __syncthreads();  // c0->B
    mstage(B, nullptr, CK_NE1, bne1, A, m0, ncol0, gid, tig, lane, false); __syncthreads(); // e->A
    mstage(A, B, CK_NEC(0), bnec + 0*H, C, m0, ncol0, gid, tig, lane, true); __syncthreads();
    mstage(C, B, CK_NEC(1), bnec + 1*H, A, m0, ncol0, gid, tig, lane, true); __syncthreads();
    mstage(A, B, CK_NEC(2), bnec + 2*H, C, m0, ncol0, gid, tig, lane, true); __syncthreads();
    mstage(C, B, CK_NEC(3), bnec + 3*H, A, m0, ncol0, gid, tig, lane, true); __syncthreads(); // e->A

#pragma unroll 2
    for (int m = 0; m < MT; m++) {
        int node = d0 + m;
        if (node < NPL)
            emb[(long)(lyr * NPL + node) * H + t] = A[m * SROW + t];
    }
}

extern "C" void kernel_launch(void* const* d_in, const int* in_sizes, int n_in,
                              void* d_out, int out_size)
{
    const float* nf      = (const float*)d_in[0];
    const int*   src     = (const int*)  d_in[1];
    const float* W_embed = (const float*)d_in[3];
    const float* b_embed = (const float*)d_in[4];
    const float* W_mp0   = (const float*)d_in[5];
    const float* b_mp0   = (const float*)d_in[6];
    const float* W_mp1   = (const float*)d_in[7];
    const float* b_mp1   = (const float*)d_in[8];
    const float* W_mpc   = (const float*)d_in[9];
    const float* b_mpc   = (const float*)d_in[10];
    const float* W_ne0   = (const float*)d_in[11];
    const float* b_ne0   = (const float*)d_in[12];
    const float* W_ne1   = (const float*)d_in[13];
    const float* b_ne1   = (const float*)d_in[14];
    const float* W_nec   = (const float*)d_in[15];
    const float* b_nec   = (const float*)d_in[16];

    float* out = (float*)d_out;

    const int smem_bytes = 3 * MT * SROW * (int)sizeof(float) + MT * KN * (int)sizeof(int);
    cudaFuncSetAttribute(layer_kernel, cudaFuncAttributeMaxDynamicSharedMemorySize, smem_bytes);

    pack_wf<<<(N_CHUNK * CH_U2 + 255) / 256, 256>>>(W_mp0, W_mp1, W_mpc, W_ne0, W_ne1, W_nec);

    const int n_nodes = L_TOT * NPL;
    embed_kernel<<<(n_nodes + EMT - 1) / EMT, NT>>>(nf, W_embed, b_embed, out, n_nodes);

    const int layer_blocks = (NPL + MT - 1) / MT;
    for (int l = 1; l < L_TOT; l++) {
        layer_kernel<<<layer_blocks, NT, smem_bytes>>>(out, src, l,
                                           b_mp0, b_mp1, b_mpc, b_ne0, b_ne1, b_nec);
    }
}